// round 5
// baseline (speedup 1.0000x reference)
#include <cuda_runtime.h>
#include <cuda_bf16.h>
#include <math.h>
#include <stdint.h>

#define BB 64
#define LL 256
#define HH 1024
#define EE 1024
#define VV 50257
#define H3 3072

// ================= scratch (__device__ globals) =============================
__device__ __align__(16) __nv_bfloat16 g_xhi[BB * 1024];
__device__ __align__(16) __nv_bfloat16 g_xlo[BB * 1024];
__device__ __align__(16) __nv_bfloat16 g_hhi[BB * 1024];
__device__ __align__(16) __nv_bfloat16 g_hlo[BB * 1024];
__device__ __align__(16) __nv_bfloat16 g_chi[BB * 1024];
__device__ __align__(16) __nv_bfloat16 g_clo[BB * 1024];
__device__ __align__(16) __nv_bfloat16 g_cat_hi[BB * 2 * HH];
__device__ __align__(16) __nv_bfloat16 g_cat_lo[BB * 2 * HH];
__device__ float g_gi[2 * BB * H3];            // k-split partials
__device__ float g_gh[2 * BB * H3];
__device__ float g_hb[BB];
__device__ float g_q[BB * HH];
__device__ float g_qpart[8 * BB * HH];
__device__ float g_scores[BB * LL];
__device__ float g_aw[BB * LL];
__device__ float g_cpart[8 * BB * HH];

// ================= helpers ===================================================
__device__ __forceinline__ uint32_t smem_u32(const void* p) {
    uint32_t a;
    asm("{ .reg .u64 t; cvta.to.shared.u64 t, %1; cvt.u32.u64 %0, t; }"
        : "=r"(a) : "l"(p));
    return a;
}

__device__ __forceinline__ void ldsm_x4(uint32_t addr, uint32_t& d0, uint32_t& d1,
                                        uint32_t& d2, uint32_t& d3) {
    asm volatile("ldmatrix.sync.aligned.m8n8.x4.shared.b16 {%0,%1,%2,%3}, [%4];"
                 : "=r"(d0), "=r"(d1), "=r"(d2), "=r"(d3) : "r"(addr));
}

__device__ __forceinline__ void mma_bf16(float* c, uint32_t a0, uint32_t a1,
                                         uint32_t a2, uint32_t a3,
                                         uint32_t b0, uint32_t b1) {
    asm volatile(
        "mma.sync.aligned.m16n8k16.row.col.f32.bf16.bf16.f32 "
        "{%0,%1,%2,%3}, {%4,%5,%6,%7}, {%8,%9}, {%0,%1,%2,%3};"
        : "+f"(c[0]), "+f"(c[1]), "+f"(c[2]), "+f"(c[3])
        : "r"(a0), "r"(a1), "r"(a2), "r"(a3), "r"(b0), "r"(b1));
}

__device__ __forceinline__ uint32_t pack_bf(float a, float b) {
    __nv_bfloat162 t = __floats2bfloat162_rn(a, b);
    return *reinterpret_cast<uint32_t*>(&t);
}

// ================= double-buffered fused-convert HMMA GEMM ==================
// C[64, n] = sum_k fp32(A[64,k]) * W[n,k]  (+bias), bf16 hi/lo 3-pass.
// A precomputed hi/lo bf16 [64 rows, stride lda]. W fp32 read exactly once,
// converted in-register; wtrans=0: W[n,k] row-major stride K;
// wtrans=1: W[k,n] row-major stride ldw (transposed access, warp-coalesced).
// Block tile 64x128, 256 threads (8 warps of 16x64). K chunk = 32.
// gridDim.z = split-K; partial z -> C + z*pstride (bias only if pstride==0).
#define STR 40                         // smem row stride in bf16 elems
#define OFF_AHI 0
#define OFF_ALO (64 * STR)
#define OFF_WHI (128 * STR)
#define OFF_WLO (256 * STR)
#define STAGE_ELEMS (384 * STR)        // 15360 elems
#define STAGE_BYTES (STAGE_ELEMS * 2)  // 30720 B
#define HMMA_SMEM (2 * STAGE_BYTES)    // 61440 B

__global__ __launch_bounds__(256, 2)
void hmma_gemm(const __nv_bfloat16* __restrict__ Ahi0, const __nv_bfloat16* __restrict__ Alo0,
               const float* __restrict__ W0, float* __restrict__ C0,
               const __nv_bfloat16* __restrict__ Ahi1, const __nv_bfloat16* __restrict__ Alo1,
               const float* __restrict__ W1, float* __restrict__ C1,
               const float* __restrict__ bias, int Ntot, int K, int ldc,
               long pstride, int lda, int ldw, int wtrans) {
    extern __shared__ __nv_bfloat16 sm[];

    const __nv_bfloat16* Ahi = blockIdx.y ? Ahi1 : Ahi0;
    const __nv_bfloat16* Alo = blockIdx.y ? Alo1 : Alo0;
    const float* W = blockIdx.y ? W1 : W0;
    float* C = (blockIdx.y ? C1 : C0) + (size_t)blockIdx.z * pstride;

    const int tid = threadIdx.x, wid = tid >> 5, lane = tid & 31;
    const int wr = wid & 3, wc = wid >> 2;
    const int n0 = blockIdx.x * 128;

    const int kper = K / gridDim.z;
    const int koff = blockIdx.z * kper;
    const int nchunks = kper >> 5;

    // staging ids
    const int r = tid >> 1, hf = tid & 1;
    const bool wv = (n0 + r) < Ntot;
    const float* wrow = W + (size_t)(n0 + r) * K + koff + hf * 16;       // !wtrans
    const float* wtb  = W + (size_t)(koff + hf * 16) * ldw + (n0 + r);   // wtrans
    const __nv_bfloat16* arow_hi = Ahi + (size_t)(r & 63) * lda + koff + hf * 16;
    const __nv_bfloat16* arow_lo = Alo + (size_t)(r & 63) * lda + koff + hf * 16;
    const bool do_a = (tid < 128);

    // ldmatrix base addresses (stage 0)
    const int am = lane >> 3, aln = lane & 7;
    const int arow2 = wr * 16 + aln + (am & 1) * 8;
    const int akoff = (am >> 1) * 8;
    const uint32_t aHiB = smem_u32(&sm[OFF_AHI + arow2 * STR + akoff]);
    const uint32_t aLoB = smem_u32(&sm[OFF_ALO + arow2 * STR + akoff]);
    const int brow_base = wc * 64 + aln + (am >> 1) * 8;
    const int bkoff = (am & 1) * 8;
    const uint32_t bHiB = smem_u32(&sm[OFF_WHI + brow_base * STR + bkoff]);
    const uint32_t bLoB = smem_u32(&sm[OFF_WLO + brow_base * STR + bkoff]);

    float acc[8][4];
#pragma unroll
    for (int i = 0; i < 8; i++)
#pragma unroll
        for (int j = 0; j < 4; j++) acc[i][j] = 0.f;

    float wreg[16];
    uint4 ahreg[2], alreg[2];

    // ---- LDG prefetch lambda-equivalents (manual) ----
#define LOAD_CHUNK(ck)                                                         \
    do {                                                                       \
        if (wv) {                                                              \
            if (!wtrans) {                                                     \
                const float4* p = (const float4*)(wrow + (ck) * 32);           \
                _Pragma("unroll") for (int i = 0; i < 4; i++) {                \
                    float4 f = p[i];                                           \
                    wreg[i * 4 + 0] = f.x; wreg[i * 4 + 1] = f.y;              \
                    wreg[i * 4 + 2] = f.z; wreg[i * 4 + 3] = f.w;              \
                }                                                              \
            } else {                                                           \
                const float* p = wtb + (size_t)(ck) * 32 * ldw;                \
                _Pragma("unroll") for (int i = 0; i < 16; i++)                 \
                    wreg[i] = p[i * ldw];                                      \
            }                                                                  \
        }                                                                      \
        if (do_a) {                                                            \
            const uint4* ph = (const uint4*)(arow_hi + (ck) * 32);             \
            const uint4* pl = (const uint4*)(arow_lo + (ck) * 32);             \
            ahreg[0] = ph[0]; ahreg[1] = ph[1];                                \
            alreg[0] = pl[0]; alreg[1] = pl[1];                                \
        }                                                                      \
    } while (0)

#define STORE_STAGE(st)                                                        \
    do {                                                                       \
        const int so = (st) * STAGE_ELEMS;                                     \
        int wb = so + OFF_WHI + r * STR + hf * 16;                             \
        int wb2 = so + OFF_WLO + r * STR + hf * 16;                            \
        _Pragma("unroll") for (int qq = 0; qq < 2; qq++) {                     \
            uint4 hv, lv;                                                      \
            float f0 = wreg[qq * 8 + 0], f1 = wreg[qq * 8 + 1];                \
            float f2 = wreg[qq * 8 + 2], f3 = wreg[qq * 8 + 3];                \
            float f4 = wreg[qq * 8 + 4], f5 = wreg[qq * 8 + 5];                \
            float f6 = wreg[qq * 8 + 6], f7 = wreg[qq * 8 + 7];                \
            float h0 = __bfloat162float(__float2bfloat16(f0));                 \
            float h1 = __bfloat162float(__float2bfloat16(f1));                 \
            float h2 = __bfloat162float(__float2bfloat16(f2));                 \
            float h3 = __bfloat162float(__float2bfloat16(f3));                 \
            float h4 = __bfloat162float(__float2bfloat16(f4));                 \
            float h5 = __bfloat162float(__float2bfloat16(f5));                 \
            float h6 = __bfloat162float(__float2bfloat16(f6));                 \
            float h7 = __bfloat162float(__float2bfloat16(f7));                 \
            hv.x = pack_bf(f0, f1); hv.y = pack_bf(f2, f3);                    \
            hv.z = pack_bf(f4, f5); hv.w = pack_bf(f6, f7);                    \
            lv.x = pack_bf(f0 - h0, f1 - h1); lv.y = pack_bf(f2 - h2, f3 - h3);\
            lv.z = pack_bf(f4 - h4, f5 - h5); lv.w = pack_bf(f6 - h6, f7 - h7);\
            *(uint4*)&sm[wb + qq * 8] = hv;                                    \
            *(uint4*)&sm[wb2 + qq * 8] = lv;                                   \
        }                                                                      \
        if (do_a) {                                                            \
            int ab = so + OFF_AHI + r * STR + hf * 16;                         \
            int ab2 = so + OFF_ALO + r * STR + hf * 16;                        \
            *(uint4*)&sm[ab + 0] = ahreg[0];                                   \
            *(uint4*)&sm[ab + 8] = ahreg[1];                                   \
            *(uint4*)&sm[ab2 + 0] = alreg[0];                                  \
            *(uint4*)&sm[ab2 + 8] = alreg[1];                                  \
        }                                                                      \
    } while (0)

    if (!wv) {
#pragma unroll
        for (int i = 0; i < 16; i++) wreg[i] = 0.f;
    }

    // prologue: chunk 0 -> stage 0
    LOAD_CHUNK(0);
    STORE_STAGE(0);
    __syncthreads();

    for (int ck = 0; ck < nchunks; ck++) {
        const bool more = (ck + 1 < nchunks);
        if (more) LOAD_CHUNK(ck + 1);

        // ---- compute from stage ck&1 ----
        const uint32_t so = (uint32_t)(ck & 1) * STAGE_BYTES;
#pragma unroll
        for (int ks = 0; ks < 2; ks++) {
            uint32_t ah0, ah1, ah2, ah3, al0, al1, al2, al3;
            ldsm_x4(aHiB + so + ks * 32, ah0, ah1, ah2, ah3);
            ldsm_x4(aLoB + so + ks * 32, al0, al1, al2, al3);
#pragma unroll
            for (int nt = 0; nt < 4; nt++) {
                const uint32_t off = so + nt * (16 * STR * 2) + ks * 32;
                uint32_t bh0, bh1, bh2, bh3, bl0, bl1, bl2, bl3;
                ldsm_x4(bHiB + off, bh0, bh1, bh2, bh3);
                ldsm_x4(bLoB + off, bl0, bl1, bl2, bl3);
                mma_bf16(acc[nt * 2],     ah0, ah1, ah2, ah3, bh0, bh1);
                mma_bf16(acc[nt * 2 + 1], ah0, ah1, ah2, ah3, bh2, bh3);
                mma_bf16(acc[nt * 2],     ah0, ah1, ah2, ah3, bl0, bl1);
                mma_bf16(acc[nt * 2 + 1], ah0, ah1, ah2, ah3, bl2, bl3);
                mma_bf16(acc[nt * 2],     al0, al1, al2, al3, bh0, bh1);
                mma_bf16(acc[nt * 2 + 1], al0, al1, al2, al3, bh2, bh3);
            }
        }

        if (more) STORE_STAGE((ck + 1) & 1);
        __syncthreads();
    }

    // ---- epilogue ----
    const int qrow = lane >> 2, qcol = (lane & 3) * 2;
    const int m0 = wr * 16 + qrow;
    const bool use_bias = (bias != nullptr) && (pstride == 0);
#pragma unroll
    for (int nt = 0; nt < 8; nt++) {
        int n = n0 + wc * 64 + nt * 8 + qcol;
        float b0v = 0.f, b1v = 0.f;
        if (use_bias) {
            if (n < Ntot) b0v = bias[n];
            if (n + 1 < Ntot) b1v = bias[n + 1];
        }
        if (n < Ntot) {
            C[(size_t)m0 * ldc + n] = acc[nt][0] + b0v;
            C[(size_t)(m0 + 8) * ldc + n] = acc[nt][2] + b0v;
        }
        if (n + 1 < Ntot) {
            C[(size_t)m0 * ldc + n + 1] = acc[nt][1] + b1v;
            C[(size_t)(m0 + 8) * ldc + n + 1] = acc[nt][3] + b1v;
        }
    }
#undef LOAD_CHUNK
#undef STORE_STAGE
}

// ================= fused hi/lo split prep (emb gather + h0) ==================
__global__ void split_all(const int* __restrict__ seq, const float* __restrict__ emb,
                          const float* __restrict__ h0,
                          __nv_bfloat16* __restrict__ xhi, __nv_bfloat16* __restrict__ xlo,
                          __nv_bfloat16* __restrict__ hhi, __nv_bfloat16* __restrict__ hlo) {
    int r = blockIdx.x, t = threadIdx.x;
    const float* src;
    __nv_bfloat16 *hi, *lo;
    int row;
    if (r < BB) {
        src = emb + (size_t)seq[r] * EE; hi = xhi; lo = xlo; row = r;
    } else {
        row = r - BB;
        src = h0 + (size_t)row * HH; hi = hhi; lo = hlo;
    }
    for (int j = t; j < 1024; j += 256) {
        float f = src[j];
        __nv_bfloat16 h = __float2bfloat16(f);
        hi[row * 1024 + j] = h;
        lo[row * 1024 + j] = __float2bfloat16(f - __bfloat162float(h));
    }
}

// ================= split-K reducers ==========================================
__global__ void reduce_ba(const float* __restrict__ P, int nsplit, int ntot,
                          int N, const float* __restrict__ bias,
                          float* __restrict__ C, int act) {
    int idx = blockIdx.x * blockDim.x + threadIdx.x;
    if (idx >= ntot) return;
    float s = 0.f;
    for (int p = 0; p < nsplit; p++) s += P[(size_t)p * ntot + idx];
    if (bias) s += bias[idx % N];
    if (act) s = tanhf(s);
    C[idx] = s;
}

// reduce 8 partials + bias + tanh + hi/lo split (for the V-GEMM's A)
__global__ void reduce_tanh_split(const float* __restrict__ P,
                                  const float* __restrict__ bias,
                                  __nv_bfloat16* __restrict__ hi,
                                  __nv_bfloat16* __restrict__ lo) {
    int idx = blockIdx.x * blockDim.x + threadIdx.x;  // 65536
    float s = 0.f;
#pragma unroll
    for (int p = 0; p < 8; p++) s += P[(size_t)p * (BB * HH) + idx];
    s = tanhf(s + bias[idx & 1023]);
    __nv_bfloat16 h = __float2bfloat16(s);
    hi[idx] = h;
    lo[idx] = __float2bfloat16(s - __bfloat162float(h));
}

// ================= fused GRU combine + hb reduction ==========================
__global__ void gru_combine_hb(const float* __restrict__ gi,
                               const float* __restrict__ gh,
                               const float* __restrict__ b_ih,
                               const float* __restrict__ b_hh,
                               const float* __restrict__ hprev,
                               const float* __restrict__ attn_b,
                               __nv_bfloat16* __restrict__ cat_hi,
                               __nv_bfloat16* __restrict__ cat_lo,
                               float* __restrict__ out_hidden,
                               float* __restrict__ hb) {
    int b = blockIdx.x, t = threadIdx.x;
    const int P = BB * H3;
    float hb_acc = 0.f;
#pragma unroll
    for (int ii = 0; ii < 4; ii++) {
        int j = t + ii * 256;
        size_t base = (size_t)b * H3 + j;
        float ir = gi[base] + gi[P + base] + b_ih[j];
        float iz = gi[base + HH] + gi[P + base + HH] + b_ih[HH + j];
        float in_ = gi[base + 2 * HH] + gi[P + base + 2 * HH] + b_ih[2 * HH + j];
        float hr = gh[base] + gh[P + base] + b_hh[j];
        float hz = gh[base + HH] + gh[P + base + HH] + b_hh[HH + j];
        float hn = gh[base + 2 * HH] + gh[P + base + 2 * HH] + b_hh[2 * HH + j];
        float r = 1.f / (1.f + expf(-(ir + hr)));
        float z = 1.f / (1.f + expf(-(iz + hz)));
        float n = tanhf(in_ + r * hn);
        float hp = hprev[(size_t)b * HH + j];
        float hnew = (1.f - z) * n + z * hp;
        out_hidden[(size_t)b * HH + j] = hnew;
        __nv_bfloat16 h = __float2bfloat16(hnew);
        cat_hi[(size_t)b * 2048 + j] = h;
        cat_lo[(size_t)b * 2048 + j] = __float2bfloat16(hnew - __bfloat162float(h));
        hb_acc += hnew * attn_b[j];
    }
    __shared__ float smr[256];
    smr[t] = hb_acc;
    __syncthreads();
    for (int st = 128; st > 0; st >>= 1) {
        if (t < st) smr[t] += smr[t + st];
        __syncthreads();
    }
    if (t == 0) hb[b] = smr[0];
}

// ================= attention kernels =========================================
__global__ void scores_kernel(const float* __restrict__ q,
                              const float* __restrict__ enc,
                              const float* __restrict__ hb,
                              float* __restrict__ scores) {
    int pair = blockIdx.x * 8 + (threadIdx.x >> 5);
    int lane = threadIdx.x & 31;
    int b = pair >> 8, l = pair & 255;
    const float* e = enc + ((size_t)l * BB + b) * HH;
    const float* qr = q + (size_t)b * HH;
    float s = 0.f;
#pragma unroll
    for (int i = 0; i < 8; i++) {
        int h = lane * 4 + i * 128;
        float4 ev = *(const float4*)(e + h);
        float4 qv = *(const float4*)(qr + h);
        s += ev.x * qv.x + ev.y * qv.y + ev.z * qv.z + ev.w * qv.w;
    }
#pragma unroll
    for (int o = 16; o > 0; o >>= 1) s += __shfl_xor_sync(0xffffffffu, s, o);
    if (lane == 0) scores[(size_t)b * LL + l] = s + hb[b];
}

__global__ void softmax_kernel(const float* __restrict__ scores,
                               float* __restrict__ aw,
                               float* __restrict__ out_attn) {
    int b = blockIdx.x, t = threadIdx.x;
    __shared__ float smr[256];
    float v = scores[(size_t)b * LL + t];
    smr[t] = v;
    __syncthreads();
    for (int s = 128; s > 0; s >>= 1) {
        if (t < s) smr[t] = fmaxf(smr[t], smr[t + s]);
        __syncthreads();
    }
    float mx = smr[0];
    __syncthreads();
    float e = expf(v - mx);
    smr[t] = e;
    __syncthreads();
    for (int s = 128; s > 0; s >>= 1) {
        if (t < s) smr[t] += smr[t + s];
        __syncthreads();
    }
    float w = e / smr[0];
    aw[(size_t)b * LL + t] = w;
    out_attn[(size_t)b * LL + t] = w;
}

__global__ void context_kernel(const float* __restrict__ aw,
                               const float* __restrict__ enc,
                               __nv_bfloat16* __restrict__ cat_hi,
                               __nv_bfloat16* __restrict__ cat_lo) {
    int b = blockIdx.x;
    int hc = blockIdx.y * 128 + threadIdx.x;
    __shared__ float aws[256];
    if (threadIdx.x < 128) {
        aws[threadIdx.x] = aw[(size_t)b * LL + threadIdx.x];
        aws[threadIdx.x + 128] = aw[(size_t)b * LL + 128 + threadIdx.x];
    }
    __syncthreads();
    float acc = 0.f;
    const float* e = enc + (size_t)b * HH + hc;
    for (int l0 = 0; l0 < LL; l0 += 16) {
        float v[16];
#pragma unroll
        for (int u = 0; u < 16; u++)
            v[u] = e[(size_t)(l0 + u) * BB * HH];
#pragma unroll
        for (int u = 0; u < 16; u++)
            acc += aws[l0 + u] * v[u];
    }
    size_t o = (size_t)b * 2048 + 1024 + hc;
    __nv_bfloat16 h = __float2bfloat16(acc);
    cat_hi[o] = h;
    cat_lo[o] = __float2bfloat16(acc - __bfloat162float(h));
}

// ================= launch =====================================================
extern "C" void kernel_launch(void* const* d_in, const int* in_sizes, int n_in,
                              void* d_out, int out_size) {
    const int*   seq  = (const int*)d_in[0];
    const float* h0   = (const float*)d_in[1];
    const float* enc  = (const float*)d_in[2];
    const float* emb  = (const float*)d_in[3];
    const float* w_ih = (const float*)d_in[4];
    const float* w_hh = (const float*)d_in[5];
    const float* b_ih = (const float*)d_in[6];
    const float* b_hh = (const float*)d_in[7];
    const float* attw = (const float*)d_in[8];
    const float* attb = (const float*)d_in[9];
    const float* cw   = (const float*)d_in[10];
    const float* cb   = (const float*)d_in[11];
    const float* ow   = (const float*)d_in[12];
    const float* ob   = (const float*)d_in[13];

    float* out        = (float*)d_out;                  // [B, V]
    float* out_hidden = out + (size_t)BB * VV;          // [B, H]
    float* out_attn   = out_hidden + (size_t)BB * HH;   // [B, L]

    cudaFuncSetAttribute(hmma_gemm, cudaFuncAttributeMaxDynamicSharedMemorySize,
                         HMMA_SMEM);

    __nv_bfloat16 *xhi, *xlo, *hhi, *hlo, *chi, *clo, *cathi, *catlo;
    float *gi, *gh, *hb, *q, *qp, *sc, *aw, *cp;
    cudaGetSymbolAddress((void**)&xhi, g_xhi);
    cudaGetSymbolAddress((void**)&xlo, g_xlo);
    cudaGetSymbolAddress((void**)&hhi, g_hhi);
    cudaGetSymbolAddress((void**)&hlo, g_hlo);
    cudaGetSymbolAddress((void**)&chi, g_chi);
    cudaGetSymbolAddress((void**)&clo, g_clo);
    cudaGetSymbolAddress((void**)&cathi, g_cat_hi);
    cudaGetSymbolAddress((void**)&catlo, g_cat_lo);
    cudaGetSymbolAddress((void**)&gi, g_gi);
    cudaGetSymbolAddress((void**)&gh, g_gh);
    cudaGetSymbolAddress((void**)&hb, g_hb);
    cudaGetSymbolAddress((void**)&q, g_q);
    cudaGetSymbolAddress((void**)&qp, g_qpart);
    cudaGetSymbolAddress((void**)&sc, g_scores);
    cudaGetSymbolAddress((void**)&aw, g_aw);
    cudaGetSymbolAddress((void**)&cp, g_cpart);

    // 1) hi/lo splits: emb gather + h0
    split_all<<<128, 256>>>(seq, emb, h0, xhi, xlo, hhi, hlo);

    // 2) GRU gate GEMMs (two problems via grid.y, split-K=2 -> 96 CTAs)
    hmma_gemm<<<dim3(24, 2, 2), 256, HMMA_SMEM>>>(
        xhi, xlo, w_ih, gi, hhi, hlo, w_hh, gh,
        nullptr, H3, EE, H3, (long)BB * H3, EE, 0, 0);

    // 3) gates -> h_new (hidden output, cat hi/lo first half, hb)
    gru_combine_hb<<<BB, 256>>>(gi, gh, b_ih, b_hh, h0, attb,
                                cathi, catlo, out_hidden, hb);

    // 4) q = h_new @ attn_w  (HMMA, transposed W access, split-K=8)
    hmma_gemm<<<dim3(8, 1, 8), 256, HMMA_SMEM>>>(
        cathi, catlo, attw, qp, cathi, catlo, attw, qp,
        nullptr, HH, HH, HH, (long)BB * HH, 2048, HH, 1);
    reduce_ba<<<(BB * HH) / 256, 256>>>(qp, 8, BB * HH, HH, nullptr, q, 0);

    // 5) scores = q . enc + hb ; softmax ; context (writes cat hi/lo 2nd half)
    scores_kernel<<<2048, 256>>>(q, enc, hb, sc);
    softmax_kernel<<<BB, 256>>>(sc, aw, out_attn);
    context_kernel<<<dim3(BB, 8), 128>>>(aw, enc, cathi, catlo);

    // 6) concat GEMM (HMMA, K=2048, split-K=8) -> tanh+split fused reduce
    hmma_gemm<<<dim3(8, 1, 8), 256, HMMA_SMEM>>>(
        cathi, catlo, cw, cp, cathi, catlo, cw, cp,
        nullptr, HH, 2048, HH, (long)BB * HH, 2048, 0, 0);
    reduce_tanh_split<<<(BB * HH) / 256, 256>>>(cp, cb, chi, clo);

    // 7) big V-GEMM (HMMA, direct write with bias)
    hmma_gemm<<<dim3((VV + 127) / 128, 1, 1), 256, HMMA_SMEM>>>(
        chi, clo, ow, out, chi, clo, ow, out,
        ob, VV, HH, VV, 0, HH, 0, 0);
}

// round 6
// speedup vs baseline: 1.2063x; 1.2063x over previous
#include <cuda_runtime.h>
#include <cuda_fp16.h>
#include <math.h>
#include <stdint.h>

#define BB 64
#define LL 256
#define HH 1024
#define EE 1024
#define VV 50257
#define H3 3072

// ================= scratch (__device__ globals) =============================
__device__ __align__(16) __half g_xhi[BB * 1024];
__device__ __align__(16) __half g_xlo[BB * 1024];
__device__ __align__(16) __half g_hhi[BB * 1024];
__device__ __align__(16) __half g_hlo[BB * 1024];
__device__ __align__(16) __half g_chi[BB * 1024];
__device__ __align__(16) __half g_cat_hi[BB * 2 * HH];
__device__ __align__(16) __half g_cat_lo[BB * 2 * HH];
__device__ float g_gi[2 * BB * H3];            // k-split partials
__device__ float g_gh[2 * BB * H3];
__device__ float g_hb[BB];
__device__ float g_q[BB * HH];
__device__ float g_qpart[8 * BB * HH];
__device__ float g_scores[BB * LL];
__device__ float g_cpart[8 * BB * HH];

// ================= helpers ===================================================
__device__ __forceinline__ uint32_t smem_u32(const void* p) {
    uint32_t a;
    asm("{ .reg .u64 t; cvta.to.shared.u64 t, %1; cvt.u32.u64 %0, t; }"
        : "=r"(a) : "l"(p));
    return a;
}

__device__ __forceinline__ void ldsm_x4(uint32_t addr, uint32_t& d0, uint32_t& d1,
                                        uint32_t& d2, uint32_t& d3) {
    asm volatile("ldmatrix.sync.aligned.m8n8.x4.shared.b16 {%0,%1,%2,%3}, [%4];"
                 : "=r"(d0), "=r"(d1), "=r"(d2), "=r"(d3) : "r"(addr));
}

__device__ __forceinline__ void mma_f16(float* c, uint32_t a0, uint32_t a1,
                                        uint32_t a2, uint32_t a3,
                                        uint32_t b0, uint32_t b1) {
    asm volatile(
        "mma.sync.aligned.m16n8k16.row.col.f32.f16.f16.f32 "
        "{%0,%1,%2,%3}, {%4,%5,%6,%7}, {%8,%9}, {%0,%1,%2,%3};"
        : "+f"(c[0]), "+f"(c[1]), "+f"(c[2]), "+f"(c[3])
        : "r"(a0), "r"(a1), "r"(a2), "r"(a3), "r"(b0), "r"(b1));
}

__device__ __forceinline__ uint32_t pack_h(float a, float b) {
    __half2 t = __floats2half2_rn(a, b);
    return *reinterpret_cast<uint32_t*>(&t);
}

// ================= double-buffered fused-convert HMMA GEMM (fp16) ===========
// C[64, n] = sum_k fp32(A[64,k]) * W[n,k] (+bias), fp16 hi/lo compensated.
// NP=3: Ahi*Whi + Ahi*Wlo + Alo*Whi (err ~2^-22) — for pre-softmax math.
// NP=2: Ahi*Whi + Ahi*Wlo           (err ~2^-12) — for the logits GEMM.
// W fp32 read exactly once, converted in-register.
// wtrans=0: W[n,k] stride K; wtrans=1: W[k,n] stride ldw.
// Block tile 64x128, 256 threads (8 warps of 16x64). K chunk = 32.
// gridDim.z = split-K; partial z -> C + z*pstride (bias only if pstride==0).
#define STR 40
#define OFF_AHI 0
#define OFF_ALO (64 * STR)
#define OFF_WHI (128 * STR)
#define OFF_WLO (256 * STR)
#define STAGE_ELEMS (384 * STR)
#define STAGE_BYTES (STAGE_ELEMS * 2)
#define HMMA_SMEM (2 * STAGE_BYTES)

template <int NP>
__global__ __launch_bounds__(256, 2)
void hmma_gemm(const __half* __restrict__ Ahi0, const __half* __restrict__ Alo0,
               const float* __restrict__ W0, float* __restrict__ C0,
               const __half* __restrict__ Ahi1, const __half* __restrict__ Alo1,
               const float* __restrict__ W1, float* __restrict__ C1,
               const float* __restrict__ bias, int Ntot, int K, int ldc,
               long pstride, int lda, int ldw, int wtrans) {
    extern __shared__ __half sm[];

    const __half* Ahi = blockIdx.y ? Ahi1 : Ahi0;
    const __half* Alo = blockIdx.y ? Alo1 : Alo0;
    const float* W = blockIdx.y ? W1 : W0;
    float* C = (blockIdx.y ? C1 : C0) + (size_t)blockIdx.z * pstride;

    const int tid = threadIdx.x, wid = tid >> 5, lane = tid & 31;
    const int wr = wid & 3, wc = wid >> 2;
    const int n0 = blockIdx.x * 128;

    const int kper = K / gridDim.z;
    const int koff = blockIdx.z * kper;
    const int nchunks = kper >> 5;

    const int r = tid >> 1, hf = tid & 1;
    const bool wv = (n0 + r) < Ntot;
    const float* wrow = W + (size_t)(n0 + r) * K + koff + hf * 16;
    const float* wtb  = W + (size_t)(koff + hf * 16) * ldw + (n0 + r);
    const __half* arow_hi = Ahi + (size_t)(r & 63) * lda + koff + hf * 16;
    const __half* arow_lo = Alo + (size_t)(r & 63) * lda + koff + hf * 16;
    const bool do_a = (tid < 128);

    const int am = lane >> 3, aln = lane & 7;
    const int arow2 = wr * 16 + aln + (am & 1) * 8;
    const int akoff = (am >> 1) * 8;
    const uint32_t aHiB = smem_u32(&sm[OFF_AHI + arow2 * STR + akoff]);
    const uint32_t aLoB = smem_u32(&sm[OFF_ALO + arow2 * STR + akoff]);
    const int brow_base = wc * 64 + aln + (am >> 1) * 8;
    const int bkoff = (am & 1) * 8;
    const uint32_t bHiB = smem_u32(&sm[OFF_WHI + brow_base * STR + bkoff]);
    const uint32_t bLoB = smem_u32(&sm[OFF_WLO + brow_base * STR + bkoff]);

    float acc[8][4];
#pragma unroll
    for (int i = 0; i < 8; i++)
#pragma unroll
        for (int j = 0; j < 4; j++) acc[i][j] = 0.f;

    float wreg[16];
    uint4 ahreg[2], alreg[2];

    auto load_chunk = [&](int ck) {
        if (wv) {
            if (!wtrans) {
                const float4* p = (const float4*)(wrow + (size_t)ck * 32);
#pragma unroll
                for (int i = 0; i < 4; i++) {
                    float4 f = p[i];
                    wreg[i * 4 + 0] = f.x; wreg[i * 4 + 1] = f.y;
                    wreg[i * 4 + 2] = f.z; wreg[i * 4 + 3] = f.w;
                }
            } else {
                const float* p = wtb + (size_t)ck * 32 * ldw;
#pragma unroll
                for (int i = 0; i < 16; i++) wreg[i] = p[(size_t)i * ldw];
            }
        }
        if (do_a) {
            const uint4* ph = (const uint4*)(arow_hi + (size_t)ck * 32);
            ahreg[0] = ph[0]; ahreg[1] = ph[1];
            if (NP == 3) {
                const uint4* pl = (const uint4*)(arow_lo + (size_t)ck * 32);
                alreg[0] = pl[0]; alreg[1] = pl[1];
            }
        }
    };

    auto store_stage = [&](int st) {
        const int so = st * STAGE_ELEMS;
        int wb = so + OFF_WHI + r * STR + hf * 16;
        int wb2 = so + OFF_WLO + r * STR + hf * 16;
#pragma unroll
        for (int qq = 0; qq < 2; qq++) {
            uint4 hv, lv;
            float f0 = wreg[qq * 8 + 0], f1 = wreg[qq * 8 + 1];
            float f2 = wreg[qq * 8 + 2], f3 = wreg[qq * 8 + 3];
            float f4 = wreg[qq * 8 + 4], f5 = wreg[qq * 8 + 5];
            float f6 = wreg[qq * 8 + 6], f7 = wreg[qq * 8 + 7];
            float h0 = __half2float(__float2half_rn(f0));
            float h1 = __half2float(__float2half_rn(f1));
            float h2 = __half2float(__float2half_rn(f2));
            float h3 = __half2float(__float2half_rn(f3));
            float h4 = __half2float(__float2half_rn(f4));
            float h5 = __half2float(__float2half_rn(f5));
            float h6 = __half2float(__float2half_rn(f6));
            float h7 = __half2float(__float2half_rn(f7));
            hv.x = pack_h(f0, f1); hv.y = pack_h(f2, f3);
            hv.z = pack_h(f4, f5); hv.w = pack_h(f6, f7);
            lv.x = pack_h(f0 - h0, f1 - h1); lv.y = pack_h(f2 - h2, f3 - h3);
            lv.z = pack_h(f4 - h4, f5 - h5); lv.w = pack_h(f6 - h6, f7 - h7);
            *(uint4*)&sm[wb + qq * 8] = hv;
            *(uint4*)&sm[wb2 + qq * 8] = lv;
        }
        if (do_a) {
            int ab = so + OFF_AHI + r * STR + hf * 16;
            *(uint4*)&sm[ab + 0] = ahreg[0];
            *(uint4*)&sm[ab + 8] = ahreg[1];
            if (NP == 3) {
                int ab2 = so + OFF_ALO + r * STR + hf * 16;
                *(uint4*)&sm[ab2 + 0] = alreg[0];
                *(uint4*)&sm[ab2 + 8] = alreg[1];
            }
        }
    };

    if (!wv) {
#pragma unroll
        for (int i = 0; i < 16; i++) wreg[i] = 0.f;
    }

    load_chunk(0);
    store_stage(0);
    __syncthreads();

    for (int ck = 0; ck < nchunks; ck++) {
        const bool more = (ck + 1 < nchunks);
        if (more) load_chunk(ck + 1);

        const uint32_t so = (uint32_t)(ck & 1) * STAGE_BYTES;
#pragma unroll
        for (int ks = 0; ks < 2; ks++) {
            uint32_t ah0, ah1, ah2, ah3;
            uint32_t al0, al1, al2, al3;
            ldsm_x4(aHiB + so + ks * 32, ah0, ah1, ah2, ah3);
            if (NP == 3) ldsm_x4(aLoB + so + ks * 32, al0, al1, al2, al3);
#pragma unroll
            for (int nt = 0; nt < 4; nt++) {
                const uint32_t off = so + nt * (16 * STR * 2) + ks * 32;
                uint32_t bh0, bh1, bh2, bh3, bl0, bl1, bl2, bl3;
                ldsm_x4(bHiB + off, bh0, bh1, bh2, bh3);
                ldsm_x4(bLoB + off, bl0, bl1, bl2, bl3);
                mma_f16(acc[nt * 2],     ah0, ah1, ah2, ah3, bh0, bh1);
                mma_f16(acc[nt * 2 + 1], ah0, ah1, ah2, ah3, bh2, bh3);
                mma_f16(acc[nt * 2],     ah0, ah1, ah2, ah3, bl0, bl1);
                mma_f16(acc[nt * 2 + 1], ah0, ah1, ah2, ah3, bl2, bl3);
                if (NP == 3) {
                    mma_f16(acc[nt * 2],     al0, al1, al2, al3, bh0, bh1);
                    mma_f16(acc[nt * 2 + 1], al0, al1, al2, al3, bh2, bh3);
                }
            }
        }

        if (more) store_stage((ck + 1) & 1);
        __syncthreads();
    }

    const int qrow = lane >> 2, qcol = (lane & 3) * 2;
    const int m0 = wr * 16 + qrow;
    const bool use_bias = (bias != nullptr) && (pstride == 0);
#pragma unroll
    for (int nt = 0; nt < 8; nt++) {
        int n = n0 + wc * 64 + nt * 8 + qcol;
        float b0v = 0.f, b1v = 0.f;
        if (use_bias) {
            if (n < Ntot) b0v = bias[n];
            if (n + 1 < Ntot) b1v = bias[n + 1];
        }
        if (n < Ntot) {
            C[(size_t)m0 * ldc + n] = acc[nt][0] + b0v;
            C[(size_t)(m0 + 8) * ldc + n] = acc[nt][2] + b0v;
        }
        if (n + 1 < Ntot) {
            C[(size_t)m0 * ldc + n + 1] = acc[nt][1] + b1v;
            C[(size_t)(m0 + 8) * ldc + n + 1] = acc[nt][3] + b1v;
        }
    }
}

// ================= fused hi/lo split prep (emb gather + h0) ==================
__global__ void split_all(const int* __restrict__ seq, const float* __restrict__ emb,
                          const float* __restrict__ h0,
                          __half* __restrict__ xhi, __half* __restrict__ xlo,
                          __half* __restrict__ hhi, __half* __restrict__ hlo) {
    int r = blockIdx.x, t = threadIdx.x;
    const float* src;
    __half *hi, *lo;
    int row;
    if (r < BB) {
        src = emb + (size_t)seq[r] * EE; hi = xhi; lo = xlo; row = r;
    } else {
        row = r - BB;
        src = h0 + (size_t)row * HH; hi = hhi; lo = hlo;
    }
    for (int j = t; j < 1024; j += 256) {
        float f = src[j];
        __half h = __float2half_rn(f);
        hi[row * 1024 + j] = h;
        lo[row * 1024 + j] = __float2half_rn(f - __half2float(h));
    }
}

// ================= split-K reducers ==========================================
__global__ void reduce_ba(const float* __restrict__ P, int nsplit, int ntot,
                          int N, const float* __restrict__ bias,
                          float* __restrict__ C, int act) {
    int idx = blockIdx.x * blockDim.x + threadIdx.x;
    if (idx >= ntot) return;
    float s = 0.f;
    for (int p = 0; p < nsplit; p++) s += P[(size_t)p * ntot + idx];
    if (bias) s += bias[idx % N];
    if (act) s = tanhf(s);
    C[idx] = s;
}

// reduce 8 partials + bias + tanh + fp16 (V-GEMM A; NP=2 uses hi only)
__global__ void reduce_tanh_split(const float* __restrict__ P,
                                  const float* __restrict__ bias,
                                  __half* __restrict__ hi) {
    int idx = blockIdx.x * blockDim.x + threadIdx.x;  // 65536
    float s = 0.f;
#pragma unroll
    for (int p = 0; p < 8; p++) s += P[(size_t)p * (BB * HH) + idx];
    s = tanhf(s + bias[idx & 1023]);
    hi[idx] = __float2half_rn(s);
}

// ================= fused GRU combine + hb reduction ==========================
__global__ void gru_combine_hb(const float* __restrict__ gi,
                               const float* __restrict__ gh,
                               const float* __restrict__ b_ih,
                               const float* __restrict__ b_hh,
                               const float* __restrict__ hprev,
                               const float* __restrict__ attn_b,
                               __half* __restrict__ cat_hi,
                               __half* __restrict__ cat_lo,
                               float* __restrict__ out_hidden,
                               float* __restrict__ hb) {
    int b = blockIdx.x, t = threadIdx.x;
    const int P = BB * H3;
    float hb_acc = 0.f;
#pragma unroll
    for (int ii = 0; ii < 4; ii++) {
        int j = t + ii * 256;
        size_t base = (size_t)b * H3 + j;
        float ir = gi[base] + gi[P + base] + b_ih[j];
        float iz = gi[base + HH] + gi[P + base + HH] + b_ih[HH + j];
        float in_ = gi[base + 2 * HH] + gi[P + base + 2 * HH] + b_ih[2 * HH + j];
        float hr = gh[base] + gh[P + base] + b_hh[j];
        float hz = gh[base + HH] + gh[P + base + HH] + b_hh[HH + j];
        float hn = gh[base + 2 * HH] + gh[P + base + 2 * HH] + b_hh[2 * HH + j];
        float r = 1.f / (1.f + expf(-(ir + hr)));
        float z = 1.f / (1.f + expf(-(iz + hz)));
        float n = tanhf(in_ + r * hn);
        float hp = hprev[(size_t)b * HH + j];
        float hnew = (1.f - z) * n + z * hp;
        out_hidden[(size_t)b * HH + j] = hnew;
        __half h = __float2half_rn(hnew);
        cat_hi[(size_t)b * 2048 + j] = h;
        cat_lo[(size_t)b * 2048 + j] = __float2half_rn(hnew - __half2float(h));
        hb_acc += hnew * attn_b[j];
    }
    __shared__ float smr[256];
    smr[t] = hb_acc;
    __syncthreads();
    for (int st = 128; st > 0; st >>= 1) {
        if (t < st) smr[t] += smr[t + st];
        __syncthreads();
    }
    if (t == 0) hb[b] = smr[0];
}

// ================= attention kernels =========================================
__global__ void scores_kernel(const float* __restrict__ q,
                              const float* __restrict__ enc,
                              const float* __restrict__ hb,
                              float* __restrict__ scores) {
    int pair = blockIdx.x * 8 + (threadIdx.x >> 5);
    int lane = threadIdx.x & 31;
    int b = pair >> 8, l = pair & 255;
    const float* e = enc + ((size_t)l * BB + b) * HH;
    const float* qr = q + (size_t)b * HH;
    float s = 0.f;
#pragma unroll
    for (int i = 0; i < 8; i++) {
        int h = lane * 4 + i * 128;
        float4 ev = *(const float4*)(e + h);
        float4 qv = *(const float4*)(qr + h);
        s += ev.x * qv.x + ev.y * qv.y + ev.z * qv.z + ev.w * qv.w;
    }
#pragma unroll
    for (int o = 16; o > 0; o >>= 1) s += __shfl_xor_sync(0xffffffffu, s, o);
    if (lane == 0) scores[(size_t)b * LL + l] = s + hb[b];
}

// fused softmax (redundant per y-block) + context slice
__global__ void softmax_context(const float* __restrict__ scores,
                                const float* __restrict__ enc,
                                float* __restrict__ out_attn,
                                __half* __restrict__ cat_hi,
                                __half* __restrict__ cat_lo) {
    int b = blockIdx.x, t = threadIdx.x;
    __shared__ float w[256];
    __shared__ float red[128];
    float v0 = scores[(size_t)b * LL + t];
    float v1 = scores[(size_t)b * LL + t + 128];
    red[t] = fmaxf(v0, v1);
    __syncthreads();
    for (int s = 64; s > 0; s >>= 1) {
        if (t < s) red[t] = fmaxf(red[t], red[t + s]);
        __syncthreads();
    }
    float mx = red[0];
    __syncthreads();
    float e0 = expf(v0 - mx), e1 = expf(v1 - mx);
    red[t] = e0 + e1;
    __syncthreads();
    for (int s = 64; s > 0; s >>= 1) {
        if (t < s) red[t] += red[t + s];
        __syncthreads();
    }
    float inv = 1.f / red[0];
    float w0 = e0 * inv, w1 = e1 * inv;
    w[t] = w0; w[t + 128] = w1;
    if (blockIdx.y == 0) {
        out_attn[(size_t)b * LL + t] = w0;
        out_attn[(size_t)b * LL + t + 128] = w1;
    }
    __syncthreads();

    int hc = blockIdx.y * 128 + t;
    float acc = 0.f;
    const float* e = enc + (size_t)b * HH + hc;
    for (int l0 = 0; l0 < LL; l0 += 16) {
        float v[16];
#pragma unroll
        for (int u = 0; u < 16; u++)
            v[u] = e[(size_t)(l0 + u) * BB * HH];
#pragma unroll
        for (int u = 0; u < 16; u++)
            acc += w[l0 + u] * v[u];
    }
    size_t o = (size_t)b * 2048 + 1024 + hc;
    __half h = __float2half_rn(acc);
    cat_hi[o] = h;
    cat_lo[o] = __float2half_rn(acc - __half2float(h));
}

// ================= launch =====================================================
extern "C" void kernel_launch(void* const* d_in, const int* in_sizes, int n_in,
                              void* d_out, int out_size) {
    const int*   seq  = (const int*)d_in[0];
    const float* h0   = (const float*)d_in[1];
    const float* enc  = (const float*)d_in[2];
    const float* emb  = (const float*)d_in[3];
    const float* w_ih = (const float*)d_in[4];
    const float* w_hh = (const float*)d_in[5];
    const float* b_ih = (const float*)d_in[6];
    const float* b_hh = (const float*)d_in[7];
    const float* attw = (const float*)d_in[8];
    const float* attb = (const float*)d_in[9];
    const float* cw   = (const float*)d_in[10];
    const float* cb   = (const float*)d_in[11];
    const float* ow   = (const float*)d_in[12];
    const float* ob   = (const float*)d_in[13];

    float* out        = (float*)d_out;                  // [B, V]
    float* out_hidden = out + (size_t)BB * VV;          // [B, H]
    float* out_attn   = out_hidden + (size_t)BB * HH;   // [B, L]

    cudaFuncSetAttribute(hmma_gemm<2>, cudaFuncAttributeMaxDynamicSharedMemorySize,
                         HMMA_SMEM);
    cudaFuncSetAttribute(hmma_gemm<3>, cudaFuncAttributeMaxDynamicSharedMemorySize,
                         HMMA_SMEM);

    __half *xhi, *xlo, *hhi, *hlo, *chi, *cathi, *catlo;
    float *gi, *gh, *hb, *q, *qp, *sc, *cp;
    cudaGetSymbolAddress((void**)&xhi, g_xhi);
    cudaGetSymbolAddress((void**)&xlo, g_xlo);
    cudaGetSymbolAddress((void**)&hhi, g_hhi);
    cudaGetSymbolAddress((void**)&hlo, g_hlo);
    cudaGetSymbolAddress((void**)&chi, g_chi);
    cudaGetSymbolAddress((void**)&cathi, g_cat_hi);
    cudaGetSymbolAddress((void**)&catlo, g_cat_lo);
    cudaGetSymbolAddress((void**)&gi, g_gi);
    cudaGetSymbolAddress((void**)&gh, g_gh);
    cudaGetSymbolAddress((void**)&hb, g_hb);
    cudaGetSymbolAddress((void**)&q, g_q);
    cudaGetSymbolAddress((void**)&qp, g_qpart);
    cudaGetSymbolAddress((void**)&sc, g_scores);
    cudaGetSymbolAddress((void**)&cp, g_cpart);

    // 1) fp16 hi/lo splits: emb gather + h0
    split_all<<<128, 256>>>(seq, emb, h0, xhi, xlo, hhi, hlo);

    // 2) GRU gate GEMMs (3-pass; two problems via grid.y, split-K=2)
    hmma_gemm<3><<<dim3(24, 2, 2), 256, HMMA_SMEM>>>(
        xhi, xlo, w_ih, gi, hhi, hlo, w_hh, gh,
        nullptr, H3, EE, H3, (long)BB * H3, EE, 0, 0);

    // 3) gates -> h_new (hidden output, cat hi/lo first half, hb)
    gru_combine_hb<<<BB, 256>>>(gi, gh, b_ih, b_hh, h0, attb,
                                cathi, catlo, out_hidden, hb);

    // 4) q = h_new @ attn_w (3-pass, transposed W, split-K=8) + reduce
    hmma_gemm<3><<<dim3(8, 1, 8), 256, HMMA_SMEM>>>(
        cathi, catlo, attw, qp, cathi, catlo, attw, qp,
        nullptr, HH, HH, HH, (long)BB * HH, 2048, HH, 1);
    reduce_ba<<<(BB * HH) / 256, 256>>>(qp, 8, BB * HH, HH, nullptr, q, 0);

    // 5) scores = q . enc + hb ; fused softmax+context
    scores_kernel<<<2048, 256>>>(q, enc, hb, sc);
    softmax_context<<<dim3(BB, 8), 128>>>(sc, enc, out_attn, cathi, catlo);

    // 6) concat GEMM (3-pass, K=2048, split-K=8) -> tanh+fp16 fused reduce
    hmma_gemm<3><<<dim3(8, 1, 8), 256, HMMA_SMEM>>>(
        cathi, catlo, cw, cp, cathi, catlo, cw, cp,
        nullptr, HH, 2048, HH, (long)BB * HH, 2048, 0, 0);
    reduce_tanh_split<<<(BB * HH) / 256, 256>>>(cp, cb, chi);

    // 7) big V-GEMM: 2-pass fp16 (A hi only) — 33% less tensor work
    hmma_gemm<2><<<dim3((VV + 127) / 128, 1, 1), 256, HMMA_SMEM>>>(
        chi, chi, ow, out, chi, chi, ow, out,
        ob, VV, HH, VV, 0, HH, 0, 0);
}